// round 6
// baseline (speedup 1.0000x reference)
#include <cuda_runtime.h>
#include <cstdint>

#define D 256
#define RT 8        // relations per block in k_rel
#define KTG 8       // k-tile floats per group per stage
#define PADB 12     // smem buffer row stride (floats): conflict-free for 16B ops
#define NT 16       // tiles per k-half (128 / KTG)
#define BUF_FLOATS (768 * PADB)

typedef unsigned long long u64;

// Scratch (no cudaMalloc allowed).
__device__ float g_sub[D];
__device__ float g_r0[D];
__device__ float g_gi[3 * D];
__device__ float g_obj[2048 * D];   // supports up to R=2048 relations (problem has R=1000)

__device__ __forceinline__ float sigmoidf_(float x) { return 1.0f / (1.0f + expf(-x)); }

__device__ __forceinline__ float wredsum(float v) {
#pragma unroll
    for (int o = 16; o; o >>= 1) v += __shfl_xor_sync(0xffffffffu, v, o);
    return v;
}

// packed f32x2 fma: acc = a*b + acc (2 packed floats)
__device__ __forceinline__ void fma2(u64& acc, u64 a, u64 b) {
    asm("fma.rn.f32x2 %0, %1, %2, %3;" : "=l"(acc) : "l"(a), "l"(b), "l"(acc));
}
__device__ __forceinline__ float unpack_sum(u64 acc) {
    float lo = __uint_as_float((unsigned)(acc & 0xffffffffu));
    float hi = __uint_as_float((unsigned)(acc >> 32));
    return lo + hi;
}

__device__ __forceinline__ void cpasync16(uint32_t dst_smem, const void* src) {
    asm volatile("cp.async.cg.shared.global [%0], [%1], 16;" :: "r"(dst_smem), "l"(src));
}
__device__ __forceinline__ void cp_commit() { asm volatile("cp.async.commit_group;"); }
__device__ __forceinline__ void cp_wait1() { asm volatile("cp.async.wait_group 1;" ::: "memory"); }
__device__ __forceinline__ void cp_wait0() { asm volatile("cp.async.wait_group 0;" ::: "memory"); }
__device__ __forceinline__ void bar_group(int id) {
    asm volatile("bar.sync %0, 256;" :: "r"(id + 1) : "memory");
}

// Coalesced warp dot: row-major W row (256 floats) with vector x.
__device__ __forceinline__ float warp_dot256(const float* __restrict__ Wrow,
                                             const float* __restrict__ x, int lane) {
    const float4* w4 = reinterpret_cast<const float4*>(Wrow);
    const float4* x4 = reinterpret_cast<const float4*>(x);
    float4 a0 = w4[lane],      b0 = x4[lane];
    float4 a1 = w4[lane + 32], b1 = x4[lane + 32];
    float s = a0.x * b0.x + a0.y * b0.y + a0.z * b0.z + a0.w * b0.w
            + a1.x * b1.x + a1.y * b1.y + a1.z * b1.z + a1.w * b1.w;
    return wredsum(s);
}

// ---------------------------------------------------------------------------
// Prolog A: sub = tanh(sub_W @ mask + sub_b).  warp-per-output.
// ---------------------------------------------------------------------------
__global__ void kA_sub(const float* __restrict__ mask, const float* __restrict__ sub_W,
                       const float* __restrict__ sub_b) {
    int lane = threadIdx.x & 31;
    int j = blockIdx.x * 8 + (threadIdx.x >> 5);
    float s = warp_dot256(sub_W + (size_t)j * D, mask, lane);
    if (lane == 0) g_sub[j] = tanhf(s + sub_b[j]);
}

// ---------------------------------------------------------------------------
// Prolog B: r0 = GRUCell(x=enc, h=sub).  warp-per-output.
// ---------------------------------------------------------------------------
__global__ void kB_r0(const float* __restrict__ enc, const float* __restrict__ W_ih,
                      const float* __restrict__ W_hh, const float* __restrict__ b_ih,
                      const float* __restrict__ b_hh) {
    int lane = threadIdx.x & 31;
    int j = blockIdx.x * 8 + (threadIdx.x >> 5);
    float gi[3], gh[3];
#pragma unroll
    for (int g = 0; g < 3; g++) {
        int row = g * D + j;
        gi[g] = warp_dot256(W_ih + (size_t)row * D, enc, lane);
        gh[g] = warp_dot256(W_hh + (size_t)row * D, g_sub, lane);
    }
    if (lane == 0) {
        float rg = sigmoidf_(gi[0] + b_ih[j] + gh[0] + b_hh[j]);
        float zg = sigmoidf_(gi[1] + b_ih[D + j] + gh[1] + b_hh[D + j]);
        float ng = tanhf(gi[2] + b_ih[2 * D + j] + rg * (gh[2] + b_hh[2 * D + j]));
        g_r0[j] = (1.0f - zg) * ng + zg * g_sub[j];
    }
}

// ---------------------------------------------------------------------------
// Prolog C: g_gi = W_ih @ r0 + b_ih  (768 outputs, shared by all edges).
// ---------------------------------------------------------------------------
__global__ void kC_gi(const float* __restrict__ W_ih, const float* __restrict__ b_ih) {
    int lane = threadIdx.x & 31;
    int j = blockIdx.x * 8 + (threadIdx.x >> 5);   // 0..767
    float s = warp_dot256(W_ih + (size_t)j * D, g_r0, lane);
    if (lane == 0) g_gi[j] = s + b_ih[j];
}

// ---------------------------------------------------------------------------
// k_rel v6: 512 threads, split-K (kh = t>>8 owns k-half), thread tt = t&255
// owns the 3 gate rows (tt, tt+256, tt+512) x 8 relations in packed-f32x2
// registers. W staged via double-buffered cp.async (per-group buffers,
// group-private named barriers). Group 1's partials go through smem; group 0
// does the GRU combine and the final tanh+store.
// smem: 4 bufs (2 groups x 2) + s_h + s_rj + s_part = 184KB -> 1 CTA/SM.
// ---------------------------------------------------------------------------
__global__ void __launch_bounds__(512, 1)
k_rel(const float* __restrict__ rel_table, const float* __restrict__ W_hh,
      const float* __restrict__ b_hh, const float* __restrict__ obj_W,
      const float* __restrict__ obj_b, int R) {
    extern __shared__ float sm[];
    float* s_h    = sm + 4 * BUF_FLOATS;          // RT * D
    float* s_rj   = s_h + RT * D;                 // RT * D
    float* s_part = s_rj + RT * D;                // 768 * 8 (reused for obj reduce)
    uint32_t smem_u32 = (uint32_t)__cvta_generic_to_shared(sm);

    int t  = threadIdx.x;
    int kh = t >> 8;            // k-group 0/1
    int tt = t & 255;
    int K0 = kh * 128;
    int rbase = blockIdx.x * RT;

    const float* buf0 = sm + (kh * 2 + 0) * BUF_FLOATS;
    const float* buf1 = sm + (kh * 2 + 1) * BUF_FLOATS;
    uint32_t bufs0 = smem_u32 + (kh * 2 + 0) * BUF_FLOATS * 4;
    uint32_t bufs1 = smem_u32 + (kh * 2 + 1) * BUF_FLOATS * 4;

    // stage h vectors (coalesced)
    for (int idx = t; idx < RT * D; idx += 512) {
        int r = idx >> 8;
        s_h[idx] = (rbase + r < R) ? rel_table[(size_t)(rbase + r) * D + (idx & 255)] : 0.0f;
    }

    // prefetch gate tile 0: thread stages rows tt, tt+256, tt+512 (2x16B each)
#pragma unroll
    for (int i = 0; i < 3; i++) {
        int row = i * 256 + tt;
#pragma unroll
        for (int half = 0; half < 2; half++)
            cpasync16(bufs0 + (row * PADB + half * 4) * 4,
                      W_hh + (size_t)row * D + K0 + half * 4);
    }
    cp_commit();
    __syncthreads();   // s_h ready

    u64 aR[RT], aZ[RT], aN[RT];
#pragma unroll
    for (int r = 0; r < RT; r++) { aR[r] = 0; aZ[r] = 0; aN[r] = 0; }

    // ---- gate phase: 16 tiles of 8 k, double-buffered ----
    for (int tile = 0; tile < NT; tile++) {
        if (tile < NT - 1) {
            int kbase = K0 + (tile + 1) * KTG;
            uint32_t db = ((tile + 1) & 1) ? bufs1 : bufs0;
#pragma unroll
            for (int i = 0; i < 3; i++) {
                int row = i * 256 + tt;
#pragma unroll
                for (int half = 0; half < 2; half++)
                    cpasync16(db + (row * PADB + half * 4) * 4,
                              W_hh + (size_t)row * D + kbase + half * 4);
            }
            cp_commit();
            cp_wait1();
        } else {
            cp_wait0();
        }
        bar_group(kh);
        const float* b = (tile & 1) ? buf1 : buf0;
#pragma unroll
        for (int kk2 = 0; kk2 < 2; kk2++) {
            int kloc = kk2 * 4;
            int kg = K0 + tile * KTG + kloc;
            ulonglong2 wr = *reinterpret_cast<const ulonglong2*>(&b[(0 * 256 + tt) * PADB + kloc]);
            ulonglong2 wz = *reinterpret_cast<const ulonglong2*>(&b[(1 * 256 + tt) * PADB + kloc]);
            ulonglong2 wn = *reinterpret_cast<const ulonglong2*>(&b[(2 * 256 + tt) * PADB + kloc]);
#pragma unroll
            for (int r = 0; r < RT; r++) {
                ulonglong2 h2 = *reinterpret_cast<const ulonglong2*>(&s_h[r * D + kg]);
                fma2(aR[r], wr.x, h2.x); fma2(aR[r], wr.y, h2.y);
                fma2(aZ[r], wz.x, h2.x); fma2(aZ[r], wz.y, h2.y);
                fma2(aN[r], wn.x, h2.x); fma2(aN[r], wn.y, h2.y);
            }
        }
        bar_group(kh);
    }

    if (kh == 1) {
#pragma unroll
        for (int r = 0; r < RT; r++) {
            s_part[(0 * 256 + tt) * 8 + r] = unpack_sum(aR[r]);
            s_part[(1 * 256 + tt) * 8 + r] = unpack_sum(aZ[r]);
            s_part[(2 * 256 + tt) * 8 + r] = unpack_sum(aN[r]);
        }
    }
    __syncthreads();   // gate partials visible; gate buffers free

    // prefetch obj tile 0 (both groups; overlaps with group 0's GRU combine)
#pragma unroll
    for (int half = 0; half < 2; half++)
        cpasync16(bufs0 + (tt * PADB + half * 4) * 4,
                  obj_W + (size_t)tt * D + K0 + half * 4);
    cp_commit();

    if (kh == 0) {
        float ir = g_gi[tt], iz = g_gi[D + tt], in_ = g_gi[2 * D + tt];
        float bhr = b_hh[tt], bhz = b_hh[D + tt], bhn = b_hh[2 * D + tt];
#pragma unroll
        for (int r = 0; r < RT; r++) {
            float AR = unpack_sum(aR[r]) + s_part[(0 * 256 + tt) * 8 + r];
            float AZ = unpack_sum(aZ[r]) + s_part[(1 * 256 + tt) * 8 + r];
            float AN = unpack_sum(aN[r]) + s_part[(2 * 256 + tt) * 8 + r];
            float rg = sigmoidf_(ir + AR + bhr);
            float zg = sigmoidf_(iz + AZ + bhz);
            float ng = tanhf(in_ + rg * (AN + bhn));
            s_rj[r * D + tt] = (1.0f - zg) * ng + zg * s_h[r * D + tt];
        }
    }
    __syncthreads();   // s_rj ready

    // ---- obj phase: tanh(obj_W @ rj + obj_b), same split-K pipeline ----
    u64 aO[RT];
#pragma unroll
    for (int r = 0; r < RT; r++) aO[r] = 0;

    for (int tile = 0; tile < NT; tile++) {
        if (tile < NT - 1) {
            int kbase = K0 + (tile + 1) * KTG;
            uint32_t db = ((tile + 1) & 1) ? bufs1 : bufs0;
#pragma unroll
            for (int half = 0; half < 2; half++)
                cpasync16(db + (tt * PADB + half * 4) * 4,
                          obj_W + (size_t)tt * D + kbase + half * 4);
            cp_commit();
            cp_wait1();
        } else {
            cp_wait0();
        }
        bar_group(kh);
        const float* b = (tile & 1) ? buf1 : buf0;
#pragma unroll
        for (int kk2 = 0; kk2 < 2; kk2++) {
            int kloc = kk2 * 4;
            int kg = K0 + tile * KTG + kloc;
            ulonglong2 wo = *reinterpret_cast<const ulonglong2*>(&b[tt * PADB + kloc]);
#pragma unroll
            for (int r = 0; r < RT; r++) {
                ulonglong2 h2 = *reinterpret_cast<const ulonglong2*>(&s_rj[r * D + kg]);
                fma2(aO[r], wo.x, h2.x); fma2(aO[r], wo.y, h2.y);
            }
        }
        bar_group(kh);
    }

    if (kh == 1) {
#pragma unroll
        for (int r = 0; r < RT; r++) s_part[tt * 8 + r] = unpack_sum(aO[r]);
    }
    __syncthreads();
    if (kh == 0) {
        float ob = obj_b[tt];
#pragma unroll
        for (int r = 0; r < RT; r++) {
            if (rbase + r < R)
                g_obj[(size_t)(rbase + r) * D + tt] =
                    tanhf(unpack_sum(aO[r]) + s_part[tt * 8 + r] + ob);
        }
    }
}

#define REL_SMEM ((4 * BUF_FLOATS + 2 * RT * D + 768 * 8) * 4)

// ---------------------------------------------------------------------------
// Single-pass scatter (+ seed row folded into block 0; seed==E never collides
// with tail_ids==0..E-1). Streaming stores keep output writes out of L2's way.
// ---------------------------------------------------------------------------
__global__ void k_scatter(const float* __restrict__ ent_table, const int* __restrict__ rel_ids,
                          const int* __restrict__ tail_ids, const int* __restrict__ tails_state,
                          const int* __restrict__ origin_ids, const int* __restrict__ seed_p,
                          float* __restrict__ out, int E) {
    if (blockIdx.x == 0) {
        int seed = *seed_p;
        out[(size_t)seed * D + threadIdx.x] = g_sub[threadIdx.x];
    }

    int warp = threadIdx.x >> 5;
    int lane = threadIdx.x & 31;
    int base = (blockIdx.x * 8 + warp) * 4;

    float4 v[4][2];
    float4* dst[4];
    bool ok[4];
#pragma unroll
    for (int i = 0; i < 4; i++) {
        int row = base + i;
        ok[i] = row < E;
        if (ok[i]) {
            int st = tails_state[row];
            const float4* src = (st == 1)
                ? reinterpret_cast<const float4*>(ent_table) + (size_t)origin_ids[row] * (D / 4)
                : reinterpret_cast<const float4*>(g_obj) + (size_t)rel_ids[row] * (D / 4);
            dst[i] = reinterpret_cast<float4*>(out) + (size_t)tail_ids[row] * (D / 4);
            v[i][0] = src[lane];
            v[i][1] = src[lane + 32];
        }
    }
#pragma unroll
    for (int i = 0; i < 4; i++) {
        if (ok[i]) {
            __stcs(&dst[i][lane], v[i][0]);
            __stcs(&dst[i][lane + 32], v[i][1]);
        }
    }
}

// ---------------------------------------------------------------------------
extern "C" void kernel_launch(void* const* d_in, const int* in_sizes, int n_in,
                              void* d_out, int out_size) {
    const float* enc       = (const float*)d_in[0];
    const float* mask      = (const float*)d_in[1];
    const float* ent_table = (const float*)d_in[2];
    const float* rel_table = (const float*)d_in[3];
    const float* W_ih      = (const float*)d_in[4];
    const float* W_hh      = (const float*)d_in[5];
    const float* b_ih      = (const float*)d_in[6];
    const float* b_hh      = (const float*)d_in[7];
    const float* sub_W     = (const float*)d_in[8];
    const float* sub_b     = (const float*)d_in[9];
    const float* obj_W     = (const float*)d_in[10];
    const float* obj_b     = (const float*)d_in[11];
    const int*   rel_ids   = (const int*)d_in[12];
    const int*   tail_ids  = (const int*)d_in[13];
    const int*   tails_st  = (const int*)d_in[14];
    const int*   origin    = (const int*)d_in[15];
    const int*   seed_p    = (const int*)d_in[16];
    float* out = (float*)d_out;

    int E = in_sizes[12];
    int R = in_sizes[3] / D;

    static bool init = false;
    if (!init) {
        cudaFuncSetAttribute(k_rel, cudaFuncAttributeMaxDynamicSharedMemorySize, REL_SMEM);
        init = true;
    }

    kA_sub<<<32, 256>>>(mask, sub_W, sub_b);
    kB_r0<<<32, 256>>>(enc, W_ih, W_hh, b_ih, b_hh);
    kC_gi<<<96, 256>>>(W_ih, b_ih);
    k_rel<<<(R + RT - 1) / RT, 512, REL_SMEM>>>(rel_table, W_hh, b_hh, obj_W, obj_b, R);
    k_scatter<<<(E + 31) / 32, 256>>>(ent_table, rel_ids, tail_ids, tails_st, origin,
                                      seed_p, out, E);
}

// round 7
// speedup vs baseline: 1.0952x; 1.0952x over previous
#include <cuda_runtime.h>
#include <cstdint>

#define D 256
#define RT 8        // relations per block (4 per half)
#define KT 32       // k-tile width staged in smem
#define PADW 36     // smem row stride (floats): conflict-free STS.128/LDS.128

typedef unsigned long long u64;

// Scratch (no cudaMalloc allowed).
__device__ float g_sub[D];
__device__ float g_r0[D];
__device__ float g_gi[3 * D];
__device__ float g_obj[2048 * D];   // supports up to R=2048 relations (problem has R=1000)

__device__ __forceinline__ float sigmoidf_(float x) { return 1.0f / (1.0f + expf(-x)); }

__device__ __forceinline__ float wredsum(float v) {
#pragma unroll
    for (int o = 16; o; o >>= 1) v += __shfl_xor_sync(0xffffffffu, v, o);
    return v;
}

// packed f32x2 fma: acc = a*b + acc (2 packed floats)
__device__ __forceinline__ void fma2(u64& acc, u64 a, u64 b) {
    asm("fma.rn.f32x2 %0, %1, %2, %3;" : "=l"(acc) : "l"(a), "l"(b), "l"(acc));
}
__device__ __forceinline__ float unpack_sum(u64 acc) {
    float lo = __uint_as_float((unsigned)(acc & 0xffffffffu));
    float hi = __uint_as_float((unsigned)(acc >> 32));
    return lo + hi;
}

// Coalesced warp dot: row-major W row (256 floats) with vector x.
__device__ __forceinline__ float warp_dot256(const float* __restrict__ Wrow,
                                             const float* __restrict__ x, int lane) {
    const float4* w4 = reinterpret_cast<const float4*>(Wrow);
    const float4* x4 = reinterpret_cast<const float4*>(x);
    float4 a0 = w4[lane],      b0 = x4[lane];
    float4 a1 = w4[lane + 32], b1 = x4[lane + 32];
    float s = a0.x * b0.x + a0.y * b0.y + a0.z * b0.z + a0.w * b0.w
            + a1.x * b1.x + a1.y * b1.y + a1.z * b1.z + a1.w * b1.w;
    return wredsum(s);
}

// ---------------------------------------------------------------------------
// Prolog A: sub = tanh(sub_W @ mask + sub_b).  warp-per-output.
// ---------------------------------------------------------------------------
__global__ void kA_sub(const float* __restrict__ mask, const float* __restrict__ sub_W,
                       const float* __restrict__ sub_b) {
    int lane = threadIdx.x & 31;
    int j = blockIdx.x * 8 + (threadIdx.x >> 5);
    float s = warp_dot256(sub_W + (size_t)j * D, mask, lane);
    if (lane == 0) g_sub[j] = tanhf(s + sub_b[j]);
}

// ---------------------------------------------------------------------------
// Prolog B: r0 = GRUCell(x=enc, h=sub).  warp-per-output.
// ---------------------------------------------------------------------------
__global__ void kB_r0(const float* __restrict__ enc, const float* __restrict__ W_ih,
                      const float* __restrict__ W_hh, const float* __restrict__ b_ih,
                      const float* __restrict__ b_hh) {
    int lane = threadIdx.x & 31;
    int j = blockIdx.x * 8 + (threadIdx.x >> 5);
    float gi[3], gh[3];
#pragma unroll
    for (int g = 0; g < 3; g++) {
        int row = g * D + j;
        gi[g] = warp_dot256(W_ih + (size_t)row * D, enc, lane);
        gh[g] = warp_dot256(W_hh + (size_t)row * D, g_sub, lane);
    }
    if (lane == 0) {
        float rg = sigmoidf_(gi[0] + b_ih[j] + gh[0] + b_hh[j]);
        float zg = sigmoidf_(gi[1] + b_ih[D + j] + gh[1] + b_hh[D + j]);
        float ng = tanhf(gi[2] + b_ih[2 * D + j] + rg * (gh[2] + b_hh[2 * D + j]));
        g_r0[j] = (1.0f - zg) * ng + zg * g_sub[j];
    }
}

// ---------------------------------------------------------------------------
// Prolog C: g_gi = W_ih @ r0 + b_ih  (768 outputs, shared by all edges).
// ---------------------------------------------------------------------------
__global__ void kC_gi(const float* __restrict__ W_ih, const float* __restrict__ b_ih) {
    int lane = threadIdx.x & 31;
    int j = blockIdx.x * 8 + (threadIdx.x >> 5);   // 0..767
    float s = warp_dot256(W_ih + (size_t)j * D, g_r0, lane);
    if (lane == 0) g_gi[j] = s + b_ih[j];
}

// ---------------------------------------------------------------------------
// k_rel v7: 512 threads, RELATION-split. Half h = t>>8 owns relations
// rbase + 4h .. rbase + 4h+3; tt = t&255 owns output dim tt. Both halves
// compute from the SAME staged W tile (identical LDS addresses = broadcast),
// so warps/SM double (16) with no extra W traffic and no cross-half reduces.
// Tile engine identical to R3 (KT=32, PADW=36, conflict-free), but one gate
// staged at a time (sW = 256 x 36 floats). smem = 53KB.
// ---------------------------------------------------------------------------
__global__ void __launch_bounds__(512, 1)
k_rel(const float* __restrict__ rel_table, const float* __restrict__ W_hh,
      const float* __restrict__ b_hh, const float* __restrict__ obj_W,
      const float* __restrict__ obj_b, int R) {
    extern __shared__ float sm[];
    float* sW   = sm;                    // 256 * PADW
    float* s_h  = sm + 256 * PADW;       // RT * D
    float* s_rj = s_h + RT * D;          // RT * D

    int t    = threadIdx.x;
    int half = t >> 8;                   // 0 or 1
    int tt   = t & 255;
    int rloc = half * 4;                 // this half's first local relation
    int rbase = blockIdx.x * RT;

    // stage h vectors (coalesced)
    for (int idx = t; idx < RT * D; idx += 512) {
        int r = idx >> 8;
        s_h[idx] = (rbase + r < R) ? rel_table[(size_t)(rbase + r) * D + (idx & 255)] : 0.0f;
    }

    u64 aG[3][4];
#pragma unroll
    for (int g = 0; g < 3; g++)
#pragma unroll
        for (int r = 0; r < 4; r++) aG[g][r] = 0;

    // ---- gate phase: 8 tiles x 3 gates; one 256x32 gate-tile staged at a time ----
    for (int tile = 0; tile < D / KT; tile++) {
#pragma unroll
        for (int g = 0; g < 3; g++) {
            __syncthreads();
            // stage 256 rows x 32 floats (2048 float4 over 512 threads, coalesced)
#pragma unroll
            for (int i = 0; i < 4; i++) {
                int lin = (i * 512 + t) * 4;
                int row = lin >> 5;
                int k   = lin & 31;
                *reinterpret_cast<float4*>(&sW[row * PADW + k]) =
                    *reinterpret_cast<const float4*>(
                        &W_hh[(size_t)(g * 256 + row) * D + tile * KT + k]);
            }
            __syncthreads();
#pragma unroll
            for (int kk = 0; kk < KT; kk += 4) {
                int kg = tile * KT + kk;
                ulonglong2 w = *reinterpret_cast<const ulonglong2*>(&sW[tt * PADW + kk]);
#pragma unroll
                for (int r = 0; r < 4; r++) {
                    ulonglong2 h2 = *reinterpret_cast<const ulonglong2*>(
                        &s_h[(rloc + r) * D + kg]);
                    fma2(aG[g][r], w.x, h2.x);
                    fma2(aG[g][r], w.y, h2.y);
                }
            }
        }
    }

    // ---- GRU combine: each half handles its own 4 relations ----
    {
        float ir = g_gi[tt], iz = g_gi[D + tt], in_ = g_gi[2 * D + tt];
        float bhr = b_hh[tt], bhz = b_hh[D + tt], bhn = b_hh[2 * D + tt];
#pragma unroll
        for (int r = 0; r < 4; r++) {
            float rg = sigmoidf_(ir + unpack_sum(aG[0][r]) + bhr);
            float zg = sigmoidf_(iz + unpack_sum(aG[1][r]) + bhz);
            float ng = tanhf(in_ + rg * (unpack_sum(aG[2][r]) + bhn));
            s_rj[(rloc + r) * D + tt] = (1.0f - zg) * ng + zg * s_h[(rloc + r) * D + tt];
        }
    }

    // ---- obj phase: tanh(obj_W @ rj + obj_b) ----
    u64 aO[4];
#pragma unroll
    for (int r = 0; r < 4; r++) aO[r] = 0;

    for (int tile = 0; tile < D / KT; tile++) {
        __syncthreads();   // first iter also orders s_rj writes before reads
#pragma unroll
        for (int i = 0; i < 4; i++) {
            int lin = (i * 512 + t) * 4;
            int row = lin >> 5;
            int k   = lin & 31;
            *reinterpret_cast<float4*>(&sW[row * PADW + k]) =
                *reinterpret_cast<const float4*>(&obj_W[(size_t)row * D + tile * KT + k]);
        }
        __syncthreads();
#pragma unroll
        for (int kk = 0; kk < KT; kk += 4) {
            int kg = tile * KT + kk;
            ulonglong2 w = *reinterpret_cast<const ulonglong2*>(&sW[tt * PADW + kk]);
#pragma unroll
            for (int r = 0; r < 4; r++) {
                ulonglong2 h2 = *reinterpret_cast<const ulonglong2*>(&s_rj[(rloc + r) * D + kg]);
                fma2(aO[r], w.x, h2.x);
                fma2(aO[r], w.y, h2.y);
            }
        }
    }

    float ob = obj_b[tt];
#pragma unroll
    for (int r = 0; r < 4; r++) {
        if (rbase + rloc + r < R)
            g_obj[(size_t)(rbase + rloc + r) * D + tt] = tanhf(unpack_sum(aO[r]) + ob);
    }
}

#define REL_SMEM ((256 * PADW + 2 * RT * D) * 4)

// ---------------------------------------------------------------------------
// Single-pass scatter (+ seed row folded into block 0; seed==E never collides
// with tail_ids==0..E-1). Streaming stores keep output writes out of L2's way.
// ---------------------------------------------------------------------------
__global__ void k_scatter(const float* __restrict__ ent_table, const int* __restrict__ rel_ids,
                          const int* __restrict__ tail_ids, const int* __restrict__ tails_state,
                          const int* __restrict__ origin_ids, const int* __restrict__ seed_p,
                          float* __restrict__ out, int E) {
    if (blockIdx.x == 0) {
        int seed = *seed_p;
        out[(size_t)seed * D + threadIdx.x] = g_sub[threadIdx.x];
    }

    int warp = threadIdx.x >> 5;
    int lane = threadIdx.x & 31;
    int base = (blockIdx.x * 8 + warp) * 4;

    float4 v[4][2];
    float4* dst[4];
    bool ok[4];
#pragma unroll
    for (int i = 0; i < 4; i++) {
        int row = base + i;
        ok[i] = row < E;
        if (ok[i]) {
            int st = tails_state[row];
            const float4* src = (st == 1)
                ? reinterpret_cast<const float4*>(ent_table) + (size_t)origin_ids[row] * (D / 4)
                : reinterpret_cast<const float4*>(g_obj) + (size_t)rel_ids[row] * (D / 4);
            dst[i] = reinterpret_cast<float4*>(out) + (size_t)tail_ids[row] * (D / 4);
            v[i][0] = src[lane];
            v[i][1] = src[lane + 32];
        }
    }
#pragma unroll
    for (int i = 0; i < 4; i++) {
        if (ok[i]) {
            __stcs(&dst[i][lane], v[i][0]);
            __stcs(&dst[i][lane + 32], v[i][1]);
        }
    }
}

// ---------------------------------------------------------------------------
extern "C" void kernel_launch(void* const* d_in, const int* in_sizes, int n_in,
                              void* d_out, int out_size) {
    const float* enc       = (const float*)d_in[0];
    const float* mask      = (const float*)d_in[1];
    const float* ent_table = (const float*)d_in[2];
    const float* rel_table = (const float*)d_in[3];
    const float* W_ih      = (const float*)d_in[4];
    const float* W_hh      = (const float*)d_in[5];
    const float* b_ih      = (const float*)d_in[6];
    const float* b_hh      = (const float*)d_in[7];
    const float* sub_W     = (const float*)d_in[8];
    const float* sub_b     = (const float*)d_in[9];
    const float* obj_W     = (const float*)d_in[10];
    const float* obj_b     = (const float*)d_in[11];
    const int*   rel_ids   = (const int*)d_in[12];
    const int*   tail_ids  = (const int*)d_in[13];
    const int*   tails_st  = (const int*)d_in[14];
    const int*   origin    = (const int*)d_in[15];
    const int*   seed_p    = (const int*)d_in[16];
    float* out = (float*)d_out;

    int E = in_sizes[12];
    int R = in_sizes[3] / D;

    static bool init = false;
    if (!init) {
        cudaFuncSetAttribute(k_rel, cudaFuncAttributeMaxDynamicSharedMemorySize, REL_SMEM);
        init = true;
    }

    kA_sub<<<32, 256>>>(mask, sub_W, sub_b);
    kB_r0<<<32, 256>>>(enc, W_ih, W_hh, b_ih, b_hh);
    kC_gi<<<96, 256>>>(W_ih, b_ih);
    k_rel<<<(R + RT - 1) / RT, 512, REL_SMEM>>>(rel_table, W_hh, b_hh, obj_W, obj_b, R);
    k_scatter<<<(E + 31) / 32, 256>>>(ent_table, rel_ids, tail_ids, tails_st, origin,
                                      seed_p, out, E);
}